// round 3
// baseline (speedup 1.0000x reference)
#include <cuda_runtime.h>
#include <cuda_bf16.h>

#define NB 16384
#define NF 26
#define FIELD_DIM 100000
#define ROWS_PER_BLOCK 4

__global__ __launch_bounds__(256) void mixdim_embbag_kernel(
    const int* __restrict__ x,
    const float* __restrict__ t0,
    const float* __restrict__ t1,
    const float* __restrict__ t2,
    const float* __restrict__ W1,
    const float* __restrict__ b1,
    const float* __restrict__ W2,
    const float* __restrict__ b2,
    float* __restrict__ out)
{
    __shared__ float s1[ROWS_PER_BLOCK][32];
    __shared__ float s2a[ROWS_PER_BLOCK][16];
    __shared__ float s2b[ROWS_PER_BLOCK][16];
    __shared__ int   sx[ROWS_PER_BLOCK][NF];

    const int tid = threadIdx.x;
    const int rg  = tid >> 6;        // row within block (0..3)
    const int t   = tid & 63;        // lane within row = output dim
    const int b   = blockIdx.x * ROWS_PER_BLOCK + rg;

    // Cooperative load of the 4*26 indices for this block's rows.
    if (tid < ROWS_PER_BLOCK * NF) {
        int r = tid / NF, c = tid % NF;
        sx[r][c] = x[(blockIdx.x * ROWS_PER_BLOCK + r) * NF + c];
    }
    __syncthreads();

    // ---- Block 0: 8 fields, 64-dim, identity projector ----
    // Hoist indices to registers so ptxas can front-batch all 8 LDGs (MLP).
    int i0[8];
    #pragma unroll
    for (int f = 0; f < 8; ++f) i0[f] = sx[rg][f] + f * FIELD_DIM;

    float acc = 0.f;
    #pragma unroll
    for (int f = 0; f < 8; ++f)
        acc += __ldg(&t0[i0[f] * 64 + t]);

    // ---- Block 1 (lanes 0..31): 8 fields, 32-dim ----
    // ---- Block 2 (lanes 32..63 split in two): 10 fields, 16-dim ----
    if (t < 32) {
        int i1[8];
        #pragma unroll
        for (int f = 0; f < 8; ++f) i1[f] = sx[rg][8 + f] + f * FIELD_DIM;
        float s = 0.f;
        #pragma unroll
        for (int f = 0; f < 8; ++f)
            s += __ldg(&t1[i1[f] * 32 + t]);
        s1[rg][t] = s;
    } else if (t < 48) {
        const int tt = t - 32;
        int i2[5];
        #pragma unroll
        for (int f = 0; f < 5; ++f) i2[f] = sx[rg][16 + f] + f * FIELD_DIM;
        float s = 0.f;
        #pragma unroll
        for (int f = 0; f < 5; ++f)
            s += __ldg(&t2[i2[f] * 16 + tt]);
        s2a[rg][tt] = s;
    } else {
        const int tt = t - 48;
        int i2[5];
        #pragma unroll
        for (int f = 0; f < 5; ++f) i2[f] = sx[rg][21 + f] + (5 + f) * FIELD_DIM;
        float s = 0.f;
        #pragma unroll
        for (int f = 0; f < 5; ++f)
            s += __ldg(&t2[i2[f] * 16 + tt]);
        s2b[rg][tt] = s;
    }
    __syncthreads();

    // ---- Projections: out_d += W1[d,:] . s1 + W2[d,:] . (s2a + s2b) ----
    const float4* w1r = reinterpret_cast<const float4*>(W1 + t * 32);
    float a1 = 0.f;
    #pragma unroll
    for (int j = 0; j < 8; ++j) {
        float4 w = __ldg(&w1r[j]);
        a1 += w.x * s1[rg][j*4+0] + w.y * s1[rg][j*4+1]
            + w.z * s1[rg][j*4+2] + w.w * s1[rg][j*4+3];
    }
    const float4* w2r = reinterpret_cast<const float4*>(W2 + t * 16);
    float a2 = 0.f;
    #pragma unroll
    for (int j = 0; j < 4; ++j) {
        float4 w = __ldg(&w2r[j]);
        a2 += w.x * (s2a[rg][j*4+0] + s2b[rg][j*4+0])
            + w.y * (s2a[rg][j*4+1] + s2b[rg][j*4+1])
            + w.z * (s2a[rg][j*4+2] + s2b[rg][j*4+2])
            + w.w * (s2a[rg][j*4+3] + s2b[rg][j*4+3]);
    }

    // Per-field bias sums to nb * b (b is zero in this dataset, kept for correctness).
    acc += a1 + a2 + 8.f * __ldg(&b1[t]) + 10.f * __ldg(&b2[t]);

    out[b * 64 + t] = acc;
}

extern "C" void kernel_launch(void* const* d_in, const int* in_sizes, int n_in,
                              void* d_out, int out_size) {
    const int*   x  = (const int*)  d_in[0];
    const float* t0 = (const float*)d_in[1];
    const float* t1 = (const float*)d_in[2];
    const float* t2 = (const float*)d_in[3];
    const float* W1 = (const float*)d_in[4];
    const float* b1 = (const float*)d_in[5];
    const float* W2 = (const float*)d_in[6];
    const float* b2 = (const float*)d_in[7];
    float* out = (float*)d_out;

    dim3 grid(NB / ROWS_PER_BLOCK);   // 4096 CTAs
    dim3 block(256);                  // 4 rows x 64 lanes
    mixdim_embbag_kernel<<<grid, block>>>(x, t0, t1, t2, W1, b1, W2, b2, out);
}

// round 5
// speedup vs baseline: 1.0381x; 1.0381x over previous
#include <cuda_runtime.h>
#include <cuda_bf16.h>

#define NB 16384
#define NF 26
#define FIELD_DIM 100000
#define WARPS_PER_CTA 8

__global__ __launch_bounds__(256) void mixdim_embbag_kernel(
    const int* __restrict__ x,
    const float* __restrict__ t0,
    const float* __restrict__ t1,
    const float* __restrict__ t2,
    const float* __restrict__ W1,
    const float* __restrict__ b1,
    const float* __restrict__ W2,
    const float* __restrict__ b2,
    float* __restrict__ out)
{
    __shared__ __align__(16) float sh1[WARPS_PER_CTA][32];
    __shared__ __align__(16) float sh2[WARPS_PER_CTA][16];

    const int w   = threadIdx.x >> 5;   // warp in CTA -> row
    const int l   = threadIdx.x & 31;   // lane
    const int row = blockIdx.x * WARPS_PER_CTA + w;

    // One warp owns one sample row. Lane f (f<26) loads index for field f.
    int xi = 0;
    if (l < NF) xi = x[row * NF + l];

    // Broadcast indices to all lanes; precompute absolute row ids.
    int i0[8], i1[8], i2[5];
    #pragma unroll
    for (int f = 0; f < 8; ++f)
        i0[f] = __shfl_sync(0xffffffffu, xi, f) + f * FIELD_DIM;
    #pragma unroll
    for (int f = 0; f < 8; ++f)
        i1[f] = __shfl_sync(0xffffffffu, xi, 8 + f) + f * FIELD_DIM;
    const int half = l >> 4;            // 0: fields 0,2,4,6,8  1: fields 1,3,5,7,9
    #pragma unroll
    for (int p = 0; p < 5; ++p) {
        int fld = 2 * p + half;
        i2[p] = __shfl_sync(0xffffffffu, xi, 16 + fld) + fld * FIELD_DIM;
    }

    // ---- Issue ALL 21 gathers back-to-back (max MLP), accumulate after ----
    float2 v0[8];
    float  v1[8];
    float  v2[5];
    const float2* t0v = reinterpret_cast<const float2*>(t0);
    const int l16 = l & 15;
    #pragma unroll
    for (int f = 0; f < 8; ++f) v0[f] = __ldg(&t0v[i0[f] * 32 + l]);      // 256B row, 2 lines
    #pragma unroll
    for (int f = 0; f < 8; ++f) v1[f] = __ldg(&t1[i1[f] * 32 + l]);       // 128B row, 1 line
    #pragma unroll
    for (int p = 0; p < 5; ++p) v2[p] = __ldg(&t2[i2[p] * 16 + l16]);     // 2 rows/instr

    // ---- Reductions ----
    float2 acc = make_float2(0.f, 0.f);
    #pragma unroll
    for (int f = 0; f < 8; ++f) { acc.x += v0[f].x; acc.y += v0[f].y; }
    float s1 = 0.f;
    #pragma unroll
    for (int f = 0; f < 8; ++f) s1 += v1[f];
    float s2 = 0.f;
    #pragma unroll
    for (int p = 0; p < 5; ++p) s2 += v2[p];
    // combine even/odd-field halves: afterwards every lane holds full s2[l&15]
    s2 += __shfl_xor_sync(0xffffffffu, s2, 16);

    sh1[w][l] = s1;
    if (l < 16) sh2[w][l] = s2;
    __syncwarp();

    // ---- Projections: lane handles output dims d0=2l, d1=2l+1 ----
    const int d0 = 2 * l, d1 = 2 * l + 1;
    const float4* w1a = reinterpret_cast<const float4*>(W1 + d0 * 32);
    const float4* w1b = reinterpret_cast<const float4*>(W1 + d1 * 32);
    const float4* s1v = reinterpret_cast<const float4*>(&sh1[w][0]);
    float a0 = 0.f, a1 = 0.f;
    #pragma unroll
    for (int j = 0; j < 8; ++j) {
        float4 s  = s1v[j];
        float4 wa = __ldg(&w1a[j]);
        float4 wb = __ldg(&w1b[j]);
        a0 += wa.x * s.x + wa.y * s.y + wa.z * s.z + wa.w * s.w;
        a1 += wb.x * s.x + wb.y * s.y + wb.z * s.z + wb.w * s.w;
    }
    const float4* w2a = reinterpret_cast<const float4*>(W2 + d0 * 16);
    const float4* w2b = reinterpret_cast<const float4*>(W2 + d1 * 16);
    const float4* s2v = reinterpret_cast<const float4*>(&sh2[w][0]);
    #pragma unroll
    for (int j = 0; j < 4; ++j) {
        float4 s  = s2v[j];
        float4 wa = __ldg(&w2a[j]);
        float4 wb = __ldg(&w2b[j]);
        a0 += wa.x * s.x + wa.y * s.y + wa.z * s.z + wa.w * s.w;
        a1 += wb.x * s.x + wb.y * s.y + wb.z * s.z + wb.w * s.w;
    }

    // bias: sums to nb*b per block (b is zero in this dataset, kept for correctness)
    acc.x += a0 + 8.f * __ldg(&b1[d0]) + 10.f * __ldg(&b2[d0]);
    acc.y += a1 + 8.f * __ldg(&b1[d1]) + 10.f * __ldg(&b2[d1]);

    reinterpret_cast<float2*>(out)[row * 32 + l] = acc;
}

extern "C" void kernel_launch(void* const* d_in, const int* in_sizes, int n_in,
                              void* d_out, int out_size) {
    const int*   x  = (const int*)  d_in[0];
    const float* t0 = (const float*)d_in[1];
    const float* t1 = (const float*)d_in[2];
    const float* t2 = (const float*)d_in[3];
    const float* W1 = (const float*)d_in[4];
    const float* b1 = (const float*)d_in[5];
    const float* W2 = (const float*)d_in[6];
    const float* b2 = (const float*)d_in[7];
    float* out = (float*)d_out;

    dim3 grid(NB / WARPS_PER_CTA);   // 2048 CTAs
    dim3 block(32 * WARPS_PER_CTA);  // 8 warps, one row each
    mixdim_embbag_kernel<<<grid, block>>>(x, t0, t1, t2, W1, b1, W2, b2, out);
}

// round 6
// speedup vs baseline: 3.3074x; 3.1860x over previous
#include <cuda_runtime.h>
#include <cuda_bf16.h>

#define NB 16384
#define NF 26
#define FIELD_DIM 100000
#define WARPS_PER_CTA 8

__global__ __launch_bounds__(256) void mixdim_embbag_kernel(
    const int* __restrict__ x,
    const float* __restrict__ t0,
    const float* __restrict__ t1,
    const float* __restrict__ t2,
    const float* __restrict__ W1,
    const float* __restrict__ b1,
    const float* __restrict__ W2,
    const float* __restrict__ b2,
    float* __restrict__ out)
{
    __shared__ __align__(16) float sh1[WARPS_PER_CTA][32];   // block-1 sums per row
    __shared__ __align__(16) float sh2[WARPS_PER_CTA][16];   // block-2 sums per row
    __shared__ float sW1[64 * 33];                            // padded: bank-conflict-free column reads
    __shared__ float sW2[64 * 17];
    __shared__ float red[4][WARPS_PER_CTA][64];               // projection partials per quarter

    const int tid = threadIdx.x;
    const int w   = tid >> 5;           // warp -> row
    const int l   = tid & 31;
    const int row = blockIdx.x * WARPS_PER_CTA + w;

    // ---- Stage W1/W2 into shared ONCE per CTA (coalesced global reads) ----
    #pragma unroll
    for (int i = 0; i < 8; ++i) {                 // W1: 64x32 = 2048 floats
        int idx = tid + 256 * i;
        int d = idx >> 5, j = idx & 31;
        sW1[d * 33 + j] = W1[idx];
    }
    #pragma unroll
    for (int i = 0; i < 4; ++i) {                 // W2: 64x16 = 1024 floats
        int idx = tid + 256 * i;
        int d = idx >> 4, j = idx & 15;
        sW2[d * 17 + j] = W2[idx];
    }

    // ---- Gather phase: one warp per row, all 21 loads batched ----
    int xi = 0;
    if (l < NF) xi = x[row * NF + l];

    int i0[8], i1[8], i2[5];
    #pragma unroll
    for (int f = 0; f < 8; ++f)
        i0[f] = __shfl_sync(0xffffffffu, xi, f) + f * FIELD_DIM;
    #pragma unroll
    for (int f = 0; f < 8; ++f)
        i1[f] = __shfl_sync(0xffffffffu, xi, 8 + f) + f * FIELD_DIM;
    const int half = l >> 4;
    #pragma unroll
    for (int p = 0; p < 5; ++p) {
        int fld = 2 * p + half;
        i2[p] = __shfl_sync(0xffffffffu, xi, 16 + fld) + fld * FIELD_DIM;
    }

    float2 v0[8];
    float  v1[8];
    float  v2[5];
    const float2* t0v = reinterpret_cast<const float2*>(t0);
    const int l16 = l & 15;
    #pragma unroll
    for (int f = 0; f < 8; ++f) v0[f] = __ldg(&t0v[i0[f] * 32 + l]);
    #pragma unroll
    for (int f = 0; f < 8; ++f) v1[f] = __ldg(&t1[i1[f] * 32 + l]);
    #pragma unroll
    for (int p = 0; p < 5; ++p) v2[p] = __ldg(&t2[i2[p] * 16 + l16]);

    float2 acc = make_float2(0.f, 0.f);
    #pragma unroll
    for (int f = 0; f < 8; ++f) { acc.x += v0[f].x; acc.y += v0[f].y; }
    float s1 = 0.f;
    #pragma unroll
    for (int f = 0; f < 8; ++f) s1 += v1[f];
    float s2 = 0.f;
    #pragma unroll
    for (int p = 0; p < 5; ++p) s2 += v2[p];
    s2 += __shfl_xor_sync(0xffffffffu, s2, 16);   // combine even/odd-field halves

    sh1[w][l] = s1;
    if (l < 16) sh2[w][l] = s2;
    __syncthreads();

    // ---- Projection phase: thread (d, q) applies its 12 weights to all 8 rows ----
    {
        const int d = tid & 63;
        const int q = tid >> 6;
        float wr1[8], wr2[4];
        #pragma unroll
        for (int j = 0; j < 8; ++j) wr1[j] = sW1[d * 33 + 8 * q + j];
        #pragma unroll
        for (int j = 0; j < 4; ++j) wr2[j] = sW2[d * 17 + 4 * q + j];
        #pragma unroll
        for (int r = 0; r < WARPS_PER_CTA; ++r) {
            float p = 0.f;
            #pragma unroll
            for (int j = 0; j < 8; ++j) p += wr1[j] * sh1[r][8 * q + j];
            #pragma unroll
            for (int j = 0; j < 4; ++j) p += wr2[j] * sh2[r][4 * q + j];
            red[q][r][d] = p;
        }
    }
    __syncthreads();

    // ---- Combine: back on the (w, l) mapping that still holds acc in regs ----
    float2 pr = make_float2(0.f, 0.f);
    #pragma unroll
    for (int qq = 0; qq < 4; ++qq) {
        pr.x += red[qq][w][2 * l];
        pr.y += red[qq][w][2 * l + 1];
    }
    const float2 bb1 = reinterpret_cast<const float2*>(b1)[l];
    const float2 bb2 = reinterpret_cast<const float2*>(b2)[l];
    acc.x += pr.x + 8.f * bb1.x + 10.f * bb2.x;   // bias sums to nb*b (zero here, kept exact)
    acc.y += pr.y + 8.f * bb1.y + 10.f * bb2.y;

    reinterpret_cast<float2*>(out)[row * 32 + l] = acc;
}

extern "C" void kernel_launch(void* const* d_in, const int* in_sizes, int n_in,
                              void* d_out, int out_size) {
    const int*   x  = (const int*)  d_in[0];
    const float* t0 = (const float*)d_in[1];
    const float* t1 = (const float*)d_in[2];
    const float* t2 = (const float*)d_in[3];
    const float* W1 = (const float*)d_in[4];
    const float* b1 = (const float*)d_in[5];
    const float* W2 = (const float*)d_in[6];
    const float* b2 = (const float*)d_in[7];
    float* out = (float*)d_out;

    dim3 grid(NB / WARPS_PER_CTA);   // 2048 CTAs
    dim3 block(32 * WARPS_PER_CTA);  // 8 warps, one row each
    mixdim_embbag_kernel<<<grid, block>>>(x, t0, t1, t2, W1, b1, W2, b2, out);
}